// round 6
// baseline (speedup 1.0000x reference)
#include <cuda_runtime.h>
#include <cuda_bf16.h>
#include <cstdint>
#include <cstddef>

// Problem constants
#define B_   2
#define S_   1024
#define HID_ 2048
#define NH_  16
#define HD_  128
#define NN_  16
#define RHID_ 1024
#define SCALE_ 0.08838834764831845f   // 128^-0.5

// ---------------------------------------------------------------------------
// Scratch (device globals: allocation-free per harness rules)
// ---------------------------------------------------------------------------
__device__ float g_q [4194304];     // (B*S, 2048) fp32
__device__ float g_k [67108864];    // (B*S*NN, 2048) fp32
__device__ float g_v [67108864];
__device__ float g_ao[4194304];

__device__ __nv_bfloat16 g_exth[33554432], g_extl[33554432];  // ext split
__device__ __nv_bfloat16 g_hidh[4194304],  g_hidl[4194304];   // hidden split
__device__ __nv_bfloat16 g_aoh [4194304],  g_aol [4194304];   // attn-out split
__device__ __nv_bfloat16 g_wqh [4194304],  g_wql [4194304];   // Wq^T split (N x K)
__device__ __nv_bfloat16 g_wkh [2097152],  g_wkl [2097152];   // Wk^T
__device__ __nv_bfloat16 g_wvh [2097152],  g_wvl [2097152];   // Wv^T
__device__ __nv_bfloat16 g_woh [4194304],  g_wol [4194304];   // Wo^T

// ---------------------------------------------------------------------------
// PTX helpers (compute_103-safe: cp.async + ldmatrix + mma.sync only)
// ---------------------------------------------------------------------------
__device__ __forceinline__ void cp16(uint32_t dst, const void* src) {
    asm volatile("cp.async.cg.shared.global [%0], [%1], 16;"
                 :: "r"(dst), "l"(src) : "memory");
}

__device__ __forceinline__ void ldsm4(uint32_t* r, uint32_t a) {
    asm volatile("ldmatrix.sync.aligned.m8n8.x4.shared.b16 {%0,%1,%2,%3}, [%4];"
                 : "=r"(r[0]), "=r"(r[1]), "=r"(r[2]), "=r"(r[3]) : "r"(a));
}

__device__ __forceinline__ void mma_bf16(float* c, const uint32_t* a,
                                         const uint32_t* b) {
    asm volatile(
        "mma.sync.aligned.m16n8k16.row.col.f32.bf16.bf16.f32 "
        "{%0,%1,%2,%3}, {%4,%5,%6,%7}, {%8,%9}, {%0,%1,%2,%3};"
        : "+f"(c[0]), "+f"(c[1]), "+f"(c[2]), "+f"(c[3])
        : "r"(a[0]), "r"(a[1]), "r"(a[2]), "r"(a[3]), "r"(b[0]), "r"(b[1]));
}

// ---------------------------------------------------------------------------
// bf16x3-split tensor-core GEMM:  C[M,N] = alpha * A[M,K] @ Bt[N,K]^T (+ R)
// A row-major (M,K) hi/lo bf16; Bt row-major (N,K) hi/lo bf16.
// CTA tile 128x128, BK=32, 256 threads (8 warps, 4x2), warp tile 32x64.
// SMEM rows padded to 40 bf16 (80B) -> conflict-free ldmatrix.
// 4-stage cp.async ring (1 sync / K-block), register-double-buffered
// fragments, term-major MMA order (no acc dependency chains).
// Stage = Ah|Al|Bh|Bl tiles @10240B = 40960B; 4 stages = 163840B.
// ---------------------------------------------------------------------------
#define GEMM_DSMEM 163840

__global__ __launch_bounds__(256) void gemm_mma_kernel(
    const __nv_bfloat16* __restrict__ Ah, const __nv_bfloat16* __restrict__ Al,
    const __nv_bfloat16* __restrict__ Bh, const __nv_bfloat16* __restrict__ Bl,
    const float* __restrict__ R, float* __restrict__ C,
    int Kdim, int Ndim, float alpha)
{
    extern __shared__ __nv_bfloat16 sm[];
    const int tid = threadIdx.x;
    const int lane = tid & 31;
    const int wid = tid >> 5;
    const int wm = wid & 3;        // 4 warp-rows (m)
    const int wn = wid >> 2;       // 2 warp-cols (n)
    const int bm = blockIdx.y * 128;
    const int bn = blockIdx.x * 128;
    const int nkb = Kdim >> 5;     // BK = 32

    const uint32_t smem_b = (uint32_t)__cvta_generic_to_shared(sm);

    float acc[2][8][4];
#pragma unroll
    for (int mt = 0; mt < 2; mt++)
#pragma unroll
        for (int nt = 0; nt < 8; nt++)
#pragma unroll
            for (int i = 0; i < 4; i++) acc[mt][nt][i] = 0.f;

    // cp.async stage load: 4 tiles x 128 rows x 4 16B-chunks = 2048 chunks,
    // 8 per thread.  tile order: 0=Ah 1=Al 2=Bh 3=Bl.  Always commits.
    auto load_stage = [&](int kb) {
        if (kb < nkb) {
            const uint32_t base = smem_b + (uint32_t)(kb & 3) * 40960u;
#pragma unroll
            for (int i = 0; i < 8; i++) {
                const int t = i >> 1;                 // compile-time tile id
                int cc = tid + (i & 1) * 256;         // 0..511 within tile
                int row = cc >> 2, u = cc & 3;
                const __nv_bfloat16* p =
                    (t == 0 ? Ah : t == 1 ? Al : t == 2 ? Bh : Bl) +
                    (size_t)((t < 2 ? bm : bn) + row) * Kdim + kb * 32 + u * 8;
                cp16(base + (uint32_t)t * 10240u + (uint32_t)row * 80u +
                     (uint32_t)u * 16u, p);
            }
        }
        asm volatile("cp.async.commit_group;" ::: "memory");
    };

    // Precomputed per-thread fragment offsets within a stage tile
    const uint32_t a_off = (uint32_t)(wm * 32 + (lane & 7) + 8 * ((lane >> 3) & 1)) * 80u
                         + (uint32_t)(8 * (lane >> 4)) * 2u;
    const uint32_t b_off = (uint32_t)(wn * 64 + (lane & 7) + 8 * (lane >> 4)) * 80u
                         + (uint32_t)(8 * ((lane >> 3) & 1)) * 2u;

    // Register-double-buffered fragments
    uint32_t ah[2][2][4], al[2][2][4];    // [buf][mt][4]
    uint32_t bh[2][8][2], bl[2][8][2];    // [buf][nt][2]

    auto ld_frags = [&](int buf, uint32_t sA, int ks) {
        const uint32_t kshift = (uint32_t)(ks * 16) * 2u;
        const uint32_t sAl = sA + 10240u;
        const uint32_t sBh = sA + 20480u;
        const uint32_t sBl = sA + 30720u;
#pragma unroll
        for (int mt = 0; mt < 2; mt++) {
            uint32_t ad = a_off + (uint32_t)(mt * 16) * 80u + kshift;
            ldsm4(ah[buf][mt], sA  + ad);
            ldsm4(al[buf][mt], sAl + ad);
        }
#pragma unroll
        for (int np = 0; np < 4; np++) {
            uint32_t bd = b_off + (uint32_t)(np * 16) * 80u + kshift;
            uint32_t rh[4], rl[4];
            ldsm4(rh, sBh + bd);
            ldsm4(rl, sBl + bd);
            bh[buf][2 * np][0] = rh[0]; bh[buf][2 * np][1] = rh[1];
            bh[buf][2 * np + 1][0] = rh[2]; bh[buf][2 * np + 1][1] = rh[3];
            bl[buf][2 * np][0] = rl[0]; bl[buf][2 * np][1] = rl[1];
            bl[buf][2 * np + 1][0] = rl[2]; bl[buf][2 * np + 1][1] = rl[3];
        }
    };

    // Prologue: 3 stages in flight
    load_stage(0);
    load_stage(1);
    load_stage(2);

    for (int kb = 0; kb < nkb; kb++) {
        // stage kb landed when <=2 groups still pending
        asm volatile("cp.async.wait_group 2;" ::: "memory");
        __syncthreads();   // all warps done reading stage kb-1; stage kb visible
        load_stage(kb + 3);

        const uint32_t sA = smem_b + (uint32_t)(kb & 3) * 40960u;
        ld_frags(0, sA, 0);

#pragma unroll
        for (int ks = 0; ks < 2; ks++) {
            if (ks == 0) ld_frags(1, sA, 1);
            const int bf = ks;
            // term-major: hi*hi, hi*lo, lo*hi — 16 independent MMAs per term
#pragma unroll
            for (int mt = 0; mt < 2; mt++)
#pragma unroll
                for (int nt = 0; nt < 8; nt++)
                    mma_bf16(acc[mt][nt], ah[bf][mt], bh[bf][nt]);
#pragma unroll
            for (int mt = 0; mt < 2; mt++)
#pragma unroll
                for (int nt = 0; nt < 8; nt++)
                    mma_bf16(acc[mt][nt], ah[bf][mt], bl[bf][nt]);
#pragma unroll
            for (int mt = 0; mt < 2; mt++)
#pragma unroll
                for (int nt = 0; nt < 8; nt++)
                    mma_bf16(acc[mt][nt], al[bf][mt], bh[bf][nt]);
        }
    }

    // Epilogue: fragment layout -> float2 stores (+alpha, +residual)
#pragma unroll
    for (int mt = 0; mt < 2; mt++) {
        int row0 = bm + wm * 32 + mt * 16 + (lane >> 2);
#pragma unroll
        for (int nt = 0; nt < 8; nt++) {
            int col = bn + wn * 64 + nt * 8 + 2 * (lane & 3);
            size_t i0 = (size_t)row0 * Ndim + col;
            size_t i1 = i0 + (size_t)8 * Ndim;
            float2 v0, v1;
            v0.x = acc[mt][nt][0] * alpha;
            v0.y = acc[mt][nt][1] * alpha;
            v1.x = acc[mt][nt][2] * alpha;
            v1.y = acc[mt][nt][3] * alpha;
            if (R) {
                const float2 r0 = *(const float2*)(R + i0);
                const float2 r1 = *(const float2*)(R + i1);
                v0.x += r0.x; v0.y += r0.y;
                v1.x += r1.x; v1.y += r1.y;
            }
            *(float2*)(C + i0) = v0;
            *(float2*)(C + i1) = v1;
        }
    }
}

// ---------------------------------------------------------------------------
// fp32 -> bf16 hi/lo split (elementwise, float4)
// ---------------------------------------------------------------------------
__global__ __launch_bounds__(256) void split_kernel(
    const float* __restrict__ x,
    __nv_bfloat16* __restrict__ hi, __nv_bfloat16* __restrict__ lo, int n4)
{
    int i = blockIdx.x * 256 + threadIdx.x;
    if (i >= n4) return;
    float4 v = ((const float4*)x)[i];
    __nv_bfloat16 h0 = __float2bfloat16(v.x);
    __nv_bfloat16 h1 = __float2bfloat16(v.y);
    __nv_bfloat16 h2 = __float2bfloat16(v.z);
    __nv_bfloat16 h3 = __float2bfloat16(v.w);
    __nv_bfloat16 l0 = __float2bfloat16(v.x - __bfloat162float(h0));
    __nv_bfloat16 l1 = __float2bfloat16(v.y - __bfloat162float(h1));
    __nv_bfloat16 l2 = __float2bfloat16(v.z - __bfloat162float(h2));
    __nv_bfloat16 l3 = __float2bfloat16(v.w - __bfloat162float(h3));
    __nv_bfloat162 ph0; ph0.x = h0; ph0.y = h1;
    __nv_bfloat162 ph1; ph1.x = h2; ph1.y = h3;
    __nv_bfloat162 pl0; pl0.x = l0; pl0.y = l1;
    __nv_bfloat162 pl1; pl1.x = l2; pl1.y = l3;
    ((__nv_bfloat162*)hi)[2 * i]     = ph0;
    ((__nv_bfloat162*)hi)[2 * i + 1] = ph1;
    ((__nv_bfloat162*)lo)[2 * i]     = pl0;
    ((__nv_bfloat162*)lo)[2 * i + 1] = pl1;
}

// ---------------------------------------------------------------------------
// Transpose + split: W (K x N fp32) -> Wt hi/lo (N x K bf16)
// ---------------------------------------------------------------------------
__global__ __launch_bounds__(256) void tsplit_kernel(
    const float* __restrict__ W,
    __nv_bfloat16* __restrict__ hi, __nv_bfloat16* __restrict__ lo, int K, int N)
{
    __shared__ float t[32][33];
    const int tx = threadIdx.x, ty = threadIdx.y;  // 32 x 8
    const int bn = blockIdx.x * 32;
    const int bk = blockIdx.y * 32;
#pragma unroll
    for (int r = 0; r < 4; r++)
        t[ty + r * 8][tx] = W[(size_t)(bk + ty + r * 8) * N + bn + tx];
    __syncthreads();
#pragma unroll
    for (int r = 0; r < 4; r++) {
        int row = ty + r * 8;
        float v = t[tx][row];
        __nv_bfloat16 h = __float2bfloat16(v);
        __nv_bfloat16 l = __float2bfloat16(v - __bfloat162float(h));
        size_t idx = (size_t)(bn + row) * K + bk + tx;
        hi[idx] = h;
        lo[idx] = l;
    }
}

// ---------------------------------------------------------------------------
// Attention (unchanged; ~111us, DRAM-bound)
// ---------------------------------------------------------------------------
__global__ __launch_bounds__(128) void attn_kernel(
    const float* __restrict__ qb, const float* __restrict__ kb,
    const float* __restrict__ vb, float* __restrict__ ob)
{
    const int h = blockIdx.x;
    const int s = blockIdx.y;
    const int b = blockIdx.z;
    const int tid = threadIdx.x;
    const int lane = tid & 31;
    const int w = tid >> 5;

    __shared__ float sc[32];
    __shared__ float pr[32];

    const float* qv = qb + ((size_t)(b * S_ + s) * NH_ + h) * HD_;
    const float4 q4 = ((const float4*)qv)[lane];

    const int pprev = (s > 0) ? (s - 1) : 0;

#pragma unroll
    for (int j = 0; j < 8; j++) {
        int i = w * 8 + j;
        int p = (i < 16) ? pprev : s;
        int n = i & 15;
        const float* kr = kb + ((size_t)((b * S_ + p) * NN_ + h)) * (NH_ * HD_) + n * HD_;
        float4 k4 = ((const float4*)kr)[lane];
        float part = q4.x * k4.x + q4.y * k4.y + q4.z * k4.z + q4.w * k4.w;
#pragma unroll
        for (int off = 16; off; off >>= 1)
            part += __shfl_xor_sync(0xffffffffu, part, off);
        if (lane == 0) sc[i] = part;
    }
    __syncthreads();

    if (tid < 32) {
        float x = sc[tid];
        float m = x;
#pragma unroll
        for (int off = 16; off; off >>= 1)
            m = fmaxf(m, __shfl_xor_sync(0xffffffffu, m, off));
        float e = expf(x - m);
        float sum = e;
#pragma unroll
        for (int off = 16; off; off >>= 1)
            sum += __shfl_xor_sync(0xffffffffu, sum, off);
        pr[tid] = e / sum;
    }
    __syncthreads();

    float acc = 0.f;
    const int d = tid;
#pragma unroll 8
    for (int i = 0; i < 32; i++) {
        int p = (i < 16) ? pprev : s;
        int n = i & 15;
        acc += pr[i] * vb[((size_t)((b * S_ + p) * NN_ + h)) * (NH_ * HD_) + n * HD_ + d];
    }
    ob[((size_t)(b * S_ + s) * NH_ + h) * HD_ + d] = acc;
}

// ---------------------------------------------------------------------------
// Launch
// ---------------------------------------------------------------------------
extern "C" void kernel_launch(void* const* d_in, const int* in_sizes, int n_in,
                              void* d_out, int out_size)
{
    const float* hidden = (const float*)d_in[0];  // (B,S,HID)
    const float* ext    = (const float*)d_in[1];  // (B,S,NN,RHID)
    const float* Wq     = (const float*)d_in[2];  // (HID, 2048)
    const float* Wk     = (const float*)d_in[3];  // (RHID, 2048)
    const float* Wv     = (const float*)d_in[4];  // (RHID, 2048)
    const float* Wo     = (const float*)d_in[5];  // (2048, HID)
    float* out = (float*)d_out;

    float *q, *k, *v, *ao;
    cudaGetSymbolAddress((void**)&q,  g_q);
    cudaGetSymbolAddress((void**)&k,  g_k);
    cudaGetSymbolAddress((void**)&v,  g_v);
    cudaGetSymbolAddress((void**)&ao, g_ao);
    __nv_bfloat16 *exth, *extl, *hidh, *hidl, *aoh, *aol;
    __nv_bfloat16 *wqh, *wql, *wkh, *wkl, *wvh, *wvl, *woh, *wol;
    cudaGetSymbolAddress((void**)&exth, g_exth);
    cudaGetSymbolAddress((void**)&extl, g_extl);
    cudaGetSymbolAddress((void**)&hidh, g_hidh);
    cudaGetSymbolAddress((void**)&hidl, g_hidl);
    cudaGetSymbolAddress((void**)&aoh,  g_aoh);
    cudaGetSymbolAddress((void**)&aol,  g_aol);
    cudaGetSymbolAddress((void**)&wqh,  g_wqh);
    cudaGetSymbolAddress((void**)&wql,  g_wql);
    cudaGetSymbolAddress((void**)&wkh,  g_wkh);
    cudaGetSymbolAddress((void**)&wkl,  g_wkl);
    cudaGetSymbolAddress((void**)&wvh,  g_wvh);
    cudaGetSymbolAddress((void**)&wvl,  g_wvl);
    cudaGetSymbolAddress((void**)&woh,  g_woh);
    cudaGetSymbolAddress((void**)&wol,  g_wol);

    cudaFuncSetAttribute(gemm_mma_kernel,
                         cudaFuncAttributeMaxDynamicSharedMemorySize, GEMM_DSMEM);

    // Splits
    split_kernel<<<4096, 256>>>(hidden, hidh, hidl, 1048576);
    split_kernel<<<32768, 256>>>(ext, exth, extl, 8388608);
    // Weight transpose+split (W^T stored N x K)
    tsplit_kernel<<<dim3(64, 64), dim3(32, 8)>>>(Wq, wqh, wql, 2048, 2048);
    tsplit_kernel<<<dim3(64, 32), dim3(32, 8)>>>(Wk, wkh, wkl, 1024, 2048);
    tsplit_kernel<<<dim3(64, 32), dim3(32, 8)>>>(Wv, wvh, wvl, 1024, 2048);
    tsplit_kernel<<<dim3(64, 64), dim3(32, 8)>>>(Wo, woh, wol, 2048, 2048);

    // Q = hidden @ Wq * SCALE            (M=2048, N=2048, K=2048)
    gemm_mma_kernel<<<dim3(16, 16), 256, GEMM_DSMEM>>>(
        hidh, hidl, wqh, wql, nullptr, q, 2048, 2048, SCALE_);
    // K = ext @ Wk                       (M=32768, N=2048, K=1024)
    gemm_mma_kernel<<<dim3(16, 256), 256, GEMM_DSMEM>>>(
        exth, extl, wkh, wkl, nullptr, k, 1024, 2048, 1.0f);
    // V = ext @ Wv
    gemm_mma_kernel<<<dim3(16, 256), 256, GEMM_DSMEM>>>(
        exth, extl, wvh, wvl, nullptr, v, 1024, 2048, 1.0f);

    // Attention
    attn_kernel<<<dim3(NH_, S_, B_), dim3(128)>>>(q, k, v, ao);

    // out = ao @ Wo + hidden
    split_kernel<<<4096, 256>>>(ao, aoh, aol, 1048576);
    gemm_mma_kernel<<<dim3(16, 16), 256, GEMM_DSMEM>>>(
        aoh, aol, woh, wol, hidden, out, 2048, 2048, 1.0f);
}

// round 7
// speedup vs baseline: 1.2444x; 1.2444x over previous
#include <cuda_runtime.h>
#include <cuda_bf16.h>
#include <cstdint>
#include <cstddef>

// Problem constants
#define B_   2
#define S_   1024
#define HID_ 2048
#define NH_  16
#define HD_  128
#define NN_  16
#define RHID_ 1024
#define SCALE_ 0.08838834764831845f   // 128^-0.5

// ---------------------------------------------------------------------------
// Scratch (device globals: allocation-free per harness rules)
// ---------------------------------------------------------------------------
__device__ float g_q [4194304];     // (B*S, 2048) fp32
__device__ float g_k [67108864];    // (B*S*NN, 2048) fp32
__device__ float g_v [67108864];
__device__ float g_ao[4194304];

__device__ __nv_bfloat16 g_exth[33554432], g_extl[33554432];  // ext split
__device__ __nv_bfloat16 g_hidh[4194304],  g_hidl[4194304];   // hidden split
__device__ __nv_bfloat16 g_aoh [4194304],  g_aol [4194304];   // attn-out split
__device__ __nv_bfloat16 g_wqh [4194304],  g_wql [4194304];   // Wq^T split (N x K)
__device__ __nv_bfloat16 g_wkh [2097152],  g_wkl [2097152];   // Wk^T
__device__ __nv_bfloat16 g_wvh [2097152],  g_wvl [2097152];   // Wv^T
__device__ __nv_bfloat16 g_woh [4194304],  g_wol [4194304];   // Wo^T

// ---------------------------------------------------------------------------
// PTX helpers (compute_103-safe: cp.async + ldmatrix + mma.sync only)
// ---------------------------------------------------------------------------
__device__ __forceinline__ void cp16(uint32_t dst, const void* src) {
    asm volatile("cp.async.cg.shared.global [%0], [%1], 16;"
                 :: "r"(dst), "l"(src) : "memory");
}

__device__ __forceinline__ void ldsm4(uint32_t* r, uint32_t a) {
    asm volatile("ldmatrix.sync.aligned.m8n8.x4.shared.b16 {%0,%1,%2,%3}, [%4];"
                 : "=r"(r[0]), "=r"(r[1]), "=r"(r[2]), "=r"(r[3]) : "r"(a));
}

__device__ __forceinline__ void mma_bf16(float* c, const uint32_t* a,
                                         const uint32_t* b) {
    asm volatile(
        "mma.sync.aligned.m16n8k16.row.col.f32.bf16.bf16.f32 "
        "{%0,%1,%2,%3}, {%4,%5,%6,%7}, {%8,%9}, {%0,%1,%2,%3};"
        : "+f"(c[0]), "+f"(c[1]), "+f"(c[2]), "+f"(c[3])
        : "r"(a[0]), "r"(a[1]), "r"(a[2]), "r"(a[3]), "r"(b[0]), "r"(b[1]));
}

// ---------------------------------------------------------------------------
// bf16x3-split tensor-core GEMM:  C[M,N] = alpha * A[M,K] @ Bt[N,K]^T (+ R)
// A row-major (M,K) hi/lo bf16; Bt row-major (N,K) hi/lo bf16.
// CTA tile 128x128, BK=32, 256 threads (8 warps, 4x2), warp tile 32x64.
// SMEM rows padded to 40 bf16 (80B) -> conflict-free ldmatrix.
// 2-stage cp.async double buffer (80KB -> 2 CTAs/SM), single fragment
// buffer, TERM-MAJOR MMA order (16 independent MMAs between acc reuse).
// __launch_bounds__(256, 2) caps regs at 128 to guarantee residency.
// ---------------------------------------------------------------------------
#define GEMM_DSMEM 81920

__global__ __launch_bounds__(256, 2) void gemm_mma_kernel(
    const __nv_bfloat16* __restrict__ Ah, const __nv_bfloat16* __restrict__ Al,
    const __nv_bfloat16* __restrict__ Bh, const __nv_bfloat16* __restrict__ Bl,
    const float* __restrict__ R, float* __restrict__ C,
    int Kdim, int Ndim, float alpha)
{
    extern __shared__ __nv_bfloat16 sm[];
    const int tid = threadIdx.x;
    const int lane = tid & 31;
    const int wid = tid >> 5;
    const int wm = wid & 3;        // 4 warp-rows (m)
    const int wn = wid >> 2;       // 2 warp-cols (n)
    const int bm = blockIdx.y * 128;
    const int bn = blockIdx.x * 128;
    const int nkb = Kdim >> 5;     // BK = 32

    const uint32_t smem_b = (uint32_t)__cvta_generic_to_shared(sm);

    float acc[2][8][4];
#pragma unroll
    for (int mt = 0; mt < 2; mt++)
#pragma unroll
        for (int nt = 0; nt < 8; nt++)
#pragma unroll
            for (int i = 0; i < 4; i++) acc[mt][nt][i] = 0.f;

    // cp.async stage load: 4 tiles x 128 rows x 4 16B-chunks = 2048 chunks,
    // 8 per thread.  tile order: 0=Ah 1=Al 2=Bh 3=Bl.
    auto load_stage = [&](int kb) {
        const uint32_t base = smem_b + (uint32_t)(kb & 1) * 40960u;
#pragma unroll
        for (int i = 0; i < 8; i++) {
            const int t = i >> 1;                 // compile-time tile id
            int cc = tid + (i & 1) * 256;         // 0..511 within tile
            int row = cc >> 2, u = cc & 3;
            const __nv_bfloat16* p =
                (t == 0 ? Ah : t == 1 ? Al : t == 2 ? Bh : Bl) +
                (size_t)((t < 2 ? bm : bn) + row) * Kdim + kb * 32 + u * 8;
            cp16(base + (uint32_t)t * 10240u + (uint32_t)row * 80u +
                 (uint32_t)u * 16u, p);
        }
        asm volatile("cp.async.commit_group;" ::: "memory");
    };

    load_stage(0);

    for (int kb = 0; kb < nkb; kb++) {
        if (kb + 1 < nkb) {
            load_stage(kb + 1);
            asm volatile("cp.async.wait_group 1;" ::: "memory");
        } else {
            asm volatile("cp.async.wait_group 0;" ::: "memory");
        }
        __syncthreads();

        const uint32_t sA  = smem_b + (uint32_t)(kb & 1) * 40960u;
        const uint32_t sAl = sA + 10240u;
        const uint32_t sBh = sA + 20480u;
        const uint32_t sBl = sA + 30720u;

#pragma unroll
        for (int ks = 0; ks < 2; ks++) {
            const int k0 = ks * 16;

            uint32_t ah[2][4], al[2][4];
#pragma unroll
            for (int mt = 0; mt < 2; mt++) {
                int row = wm * 32 + mt * 16 + (lane & 7) + 8 * ((lane >> 3) & 1);
                int col = k0 + 8 * (lane >> 4);
                uint32_t ad = (uint32_t)row * 80u + (uint32_t)col * 2u;
                ldsm4(ah[mt], sA  + ad);
                ldsm4(al[mt], sAl + ad);
            }

            uint32_t bh[8][2], bl[8][2];
#pragma unroll
            for (int np = 0; np < 4; np++) {      // x4 covers two n8 tiles
                int row = wn * 64 + np * 16 + (lane & 7) + 8 * (lane >> 4);
                int col = k0 + 8 * ((lane >> 3) & 1);
                uint32_t bd = (uint32_t)row * 80u + (uint32_t)col * 2u;
                uint32_t rh[4], rl[4];
                ldsm4(rh, sBh + bd);
                ldsm4(rl, sBl + bd);
                bh[2 * np][0] = rh[0]; bh[2 * np][1] = rh[1];
                bh[2 * np + 1][0] = rh[2]; bh[2 * np + 1][1] = rh[3];
                bl[2 * np][0] = rl[0]; bl[2 * np][1] = rl[1];
                bl[2 * np + 1][0] = rl[2]; bl[2 * np + 1][1] = rl[3];
            }

            // TERM-MAJOR: 16 independent MMAs between accumulator reuse.
#pragma unroll
            for (int mt = 0; mt < 2; mt++)
#pragma unroll
                for (int nt = 0; nt < 8; nt++)
                    mma_bf16(acc[mt][nt], ah[mt], bh[nt]);   // hi*hi
#pragma unroll
            for (int mt = 0; mt < 2; mt++)
#pragma unroll
                for (int nt = 0; nt < 8; nt++)
                    mma_bf16(acc[mt][nt], ah[mt], bl[nt]);   // hi*lo
#pragma unroll
            for (int mt = 0; mt < 2; mt++)
#pragma unroll
                for (int nt = 0; nt < 8; nt++)
                    mma_bf16(acc[mt][nt], al[mt], bh[nt]);   // lo*hi
        }
        __syncthreads();
    }

    // Epilogue: fragment layout -> float2 stores (+alpha, +residual)
#pragma unroll
    for (int mt = 0; mt < 2; mt++) {
        int row0 = bm + wm * 32 + mt * 16 + (lane >> 2);
#pragma unroll
        for (int nt = 0; nt < 8; nt++) {
            int col = bn + wn * 64 + nt * 8 + 2 * (lane & 3);
            size_t i0 = (size_t)row0 * Ndim + col;
            size_t i1 = i0 + (size_t)8 * Ndim;
            float2 v0, v1;
            v0.x = acc[mt][nt][0] * alpha;
            v0.y = acc[mt][nt][1] * alpha;
            v1.x = acc[mt][nt][2] * alpha;
            v1.y = acc[mt][nt][3] * alpha;
            if (R) {
                const float2 r0 = *(const float2*)(R + i0);
                const float2 r1 = *(const float2*)(R + i1);
                v0.x += r0.x; v0.y += r0.y;
                v1.x += r1.x; v1.y += r1.y;
            }
            *(float2*)(C + i0) = v0;
            *(float2*)(C + i1) = v1;
        }
    }
}

// ---------------------------------------------------------------------------
// fp32 -> bf16 hi/lo split (elementwise, float4)
// ---------------------------------------------------------------------------
__global__ __launch_bounds__(256) void split_kernel(
    const float* __restrict__ x,
    __nv_bfloat16* __restrict__ hi, __nv_bfloat16* __restrict__ lo, int n4)
{
    int i = blockIdx.x * 256 + threadIdx.x;
    if (i >= n4) return;
    float4 v = ((const float4*)x)[i];
    __nv_bfloat16 h0 = __float2bfloat16(v.x);
    __nv_bfloat16 h1 = __float2bfloat16(v.y);
    __nv_bfloat16 h2 = __float2bfloat16(v.z);
    __nv_bfloat16 h3 = __float2bfloat16(v.w);
    __nv_bfloat16 l0 = __float2bfloat16(v.x - __bfloat162float(h0));
    __nv_bfloat16 l1 = __float2bfloat16(v.y - __bfloat162float(h1));
    __nv_bfloat16 l2 = __float2bfloat16(v.z - __bfloat162float(h2));
    __nv_bfloat16 l3 = __float2bfloat16(v.w - __bfloat162float(h3));
    __nv_bfloat162 ph0; ph0.x = h0; ph0.y = h1;
    __nv_bfloat162 ph1; ph1.x = h2; ph1.y = h3;
    __nv_bfloat162 pl0; pl0.x = l0; pl0.y = l1;
    __nv_bfloat162 pl1; pl1.x = l2; pl1.y = l3;
    ((__nv_bfloat162*)hi)[2 * i]     = ph0;
    ((__nv_bfloat162*)hi)[2 * i + 1] = ph1;
    ((__nv_bfloat162*)lo)[2 * i]     = pl0;
    ((__nv_bfloat162*)lo)[2 * i + 1] = pl1;
}

// ---------------------------------------------------------------------------
// Transpose + split: W (K x N fp32) -> Wt hi/lo (N x K bf16)
// ---------------------------------------------------------------------------
__global__ __launch_bounds__(256) void tsplit_kernel(
    const float* __restrict__ W,
    __nv_bfloat16* __restrict__ hi, __nv_bfloat16* __restrict__ lo, int K, int N)
{
    __shared__ float t[32][33];
    const int tx = threadIdx.x, ty = threadIdx.y;  // 32 x 8
    const int bn = blockIdx.x * 32;
    const int bk = blockIdx.y * 32;
#pragma unroll
    for (int r = 0; r < 4; r++)
        t[ty + r * 8][tx] = W[(size_t)(bk + ty + r * 8) * N + bn + tx];
    __syncthreads();
#pragma unroll
    for (int r = 0; r < 4; r++) {
        int row = ty + r * 8;
        float v = t[tx][row];
        __nv_bfloat16 h = __float2bfloat16(v);
        __nv_bfloat16 l = __float2bfloat16(v - __bfloat162float(h));
        size_t idx = (size_t)(bn + row) * K + bk + tx;
        hi[idx] = h;
        lo[idx] = l;
    }
}

// ---------------------------------------------------------------------------
// Attention (unchanged; ~111us, DRAM-bound)
// ---------------------------------------------------------------------------
__global__ __launch_bounds__(128) void attn_kernel(
    const float* __restrict__ qb, const float* __restrict__ kb,
    const float* __restrict__ vb, float* __restrict__ ob)
{
    const int h = blockIdx.x;
    const int s = blockIdx.y;
    const int b = blockIdx.z;
    const int tid = threadIdx.x;
    const int lane = tid & 31;
    const int w = tid >> 5;

    __shared__ float sc[32];
    __shared__ float pr[32];

    const float* qv = qb + ((size_t)(b * S_ + s) * NH_ + h) * HD_;
    const float4 q4 = ((const float4*)qv)[lane];

    const int pprev = (s > 0) ? (s - 1) : 0;

#pragma unroll
    for (int j = 0; j < 8; j++) {
        int i = w * 8 + j;
        int p = (i < 16) ? pprev : s;
        int n = i & 15;
        const float* kr = kb + ((size_t)((b * S_ + p) * NN_ + h)) * (NH_ * HD_) + n * HD_;
        float4 k4 = ((const float4*)kr)[lane];
        float part = q4.x * k4.x + q4.y * k4.y + q4.z * k4.z + q4.w * k4.w;
#pragma unroll
        for (int off = 16; off; off >>= 1)
            part += __shfl_xor_sync(0xffffffffu, part, off);
        if (lane == 0) sc[i] = part;
    }
    __syncthreads();

    if (tid < 32) {
        float x = sc[tid];
        float m = x;
#pragma unroll
        for (int off = 16; off; off >>= 1)
            m = fmaxf(m, __shfl_xor_sync(0xffffffffu, m, off));
        float e = expf(x - m);
        float sum = e;
#pragma unroll
        for (int off = 16; off; off >>= 1)
            sum += __shfl_xor_sync(0xffffffffu, sum, off);
        pr[tid] = e / sum;
    }
    __syncthreads();

    float acc = 0.f;
    const int d = tid;
#pragma unroll 8
    for (int i = 0; i < 32; i++) {
        int p = (i < 16) ? pprev : s;
        int n = i & 15;
        acc += pr[i] * vb[((size_t)((b * S_ + p) * NN_ + h)) * (NH_ * HD_) + n * HD_ + d];
    }
    ob[((size_t)(b * S_ + s) * NH_ + h) * HD_ + d] = acc;
}

// ---------------------------------------------------------------------------
// Launch
// ---------------------------------------------------------------------------
extern "C" void kernel_launch(void* const* d_in, const int* in_sizes, int n_in,
                              void* d_out, int out_size)
{
    const float* hidden = (const float*)d_in[0];  // (B,S,HID)
    const float* ext    = (const float*)d_in[1];  // (B,S,NN,RHID)
    const float* Wq     = (const float*)d_in[2];  // (HID, 2048)
    const float* Wk     = (const float*)d_in[3];  // (RHID, 2048)
    const float* Wv     = (const float*)d_in[4];  // (RHID, 2048)
    const float* Wo     = (const float*)d_in[5];  // (2048, HID)
    float* out = (float*)d_out;

    float *q, *k, *v, *ao;
    cudaGetSymbolAddress((void**)&q,  g_q);
    cudaGetSymbolAddress((void**)&k,  g_k);
    cudaGetSymbolAddress((void**)&v,  g_v);
    cudaGetSymbolAddress((void**)&ao, g_ao);
    __nv_bfloat16 *exth, *extl, *hidh, *hidl, *aoh, *aol;
    __nv_bfloat16 *wqh, *wql, *wkh, *wkl, *wvh, *wvl, *woh, *wol;
    cudaGetSymbolAddress((void**)&exth, g_exth);
    cudaGetSymbolAddress((void**)&extl, g_extl);
    cudaGetSymbolAddress((void**)&hidh, g_hidh);
    cudaGetSymbolAddress((void**)&hidl, g_hidl);
    cudaGetSymbolAddress((void**)&aoh,  g_aoh);
    cudaGetSymbolAddress((void**)&aol,  g_aol);
    cudaGetSymbolAddress((void**)&wqh,  g_wqh);
    cudaGetSymbolAddress((void**)&wql,  g_wql);
    cudaGetSymbolAddress((void**)&wkh,  g_wkh);
    cudaGetSymbolAddress((void**)&wkl,  g_wkl);
    cudaGetSymbolAddress((void**)&wvh,  g_wvh);
    cudaGetSymbolAddress((void**)&wvl,  g_wvl);
    cudaGetSymbolAddress((void**)&woh,  g_woh);
    cudaGetSymbolAddress((void**)&wol,  g_wol);

    cudaFuncSetAttribute(gemm_mma_kernel,
                         cudaFuncAttributeMaxDynamicSharedMemorySize, GEMM_DSMEM);

    // Splits
    split_kernel<<<4096, 256>>>(hidden, hidh, hidl, 1048576);
    split_kernel<<<32768, 256>>>(ext, exth, extl, 8388608);
    // Weight transpose+split (W^T stored N x K)
    tsplit_kernel<<<dim3(64, 64), dim3(32, 8)>>>(Wq, wqh, wql, 2048, 2048);
    tsplit_kernel<<<dim3(64, 32), dim3(32, 8)>>>(Wk, wkh, wkl, 1024, 2048);
    tsplit_kernel<<<dim3(64, 32), dim3(32, 8)>>>(Wv, wvh, wvl, 1024, 2048);
    tsplit_kernel<<<dim3(64, 64), dim3(32, 8)>>>(Wo, woh, wol, 2048, 2048);

    // Q = hidden @ Wq * SCALE            (M=2048, N=2048, K=2048)
    gemm_mma_kernel<<<dim3(16, 16), 256, GEMM_DSMEM>>>(
        hidh, hidl, wqh, wql, nullptr, q, 2048, 2048, SCALE_);
    // K = ext @ Wk                       (M=32768, N=2048, K=1024)
    gemm_mma_kernel<<<dim3(16, 256), 256, GEMM_DSMEM>>>(
        exth, extl, wkh, wkl, nullptr, k, 1024, 2048, 1.0f);
    // V = ext @ Wv
    gemm_mma_kernel<<<dim3(16, 256), 256, GEMM_DSMEM>>>(
        exth, extl, wvh, wvl, nullptr, v, 1024, 2048, 1.0f);

    // Attention
    attn_kernel<<<dim3(NH_, S_, B_), dim3(128)>>>(q, k, v, ao);

    // out = ao @ Wo + hidden
    split_kernel<<<4096, 256>>>(ao, aoh, aol, 1048576);
    gemm_mma_kernel<<<dim3(16, 16), 256, GEMM_DSMEM>>>(
        aoh, aol, woh, wol, hidden, out, 2048, 2048, 1.0f);
}

// round 8
// speedup vs baseline: 1.4072x; 1.1308x over previous
#include <cuda_runtime.h>
#include <cuda_bf16.h>
#include <cstdint>
#include <cstddef>

// Problem constants
#define B_   2
#define S_   1024
#define HID_ 2048
#define NH_  16
#define HD_  128
#define NN_  16
#define RHID_ 1024
#define SCALE_ 0.08838834764831845f   // 128^-0.5

// ---------------------------------------------------------------------------
// Scratch (device globals: allocation-free per harness rules)
// ---------------------------------------------------------------------------
__device__ float g_q [4194304];     // (B*S, 2048) fp32
__device__ float g_k [67108864];    // (B*S*NN, 2048) fp32
__device__ float g_v [67108864];
__device__ float g_ao[4194304];

__device__ __nv_bfloat16 g_exth[33554432], g_extl[33554432];  // ext split
__device__ __nv_bfloat16 g_hidh[4194304],  g_hidl[4194304];   // hidden split
__device__ __nv_bfloat16 g_aoh [4194304],  g_aol [4194304];   // attn-out split
__device__ __nv_bfloat16 g_wqh [4194304],  g_wql [4194304];   // Wq^T split (N x K)
__device__ __nv_bfloat16 g_wkh [2097152],  g_wkl [2097152];   // Wk^T
__device__ __nv_bfloat16 g_wvh [2097152],  g_wvl [2097152];   // Wv^T
__device__ __nv_bfloat16 g_woh [4194304],  g_wol [4194304];   // Wo^T

// ---------------------------------------------------------------------------
// PTX helpers (compute_103-safe: cp.async + ldmatrix + mma.sync only)
// ---------------------------------------------------------------------------
__device__ __forceinline__ void cp16(uint32_t dst, const void* src) {
    asm volatile("cp.async.cg.shared.global [%0], [%1], 16;"
                 :: "r"(dst), "l"(src) : "memory");
}

__device__ __forceinline__ void ldsm4(uint32_t* r, uint32_t a) {
    asm volatile("ldmatrix.sync.aligned.m8n8.x4.shared.b16 {%0,%1,%2,%3}, [%4];"
                 : "=r"(r[0]), "=r"(r[1]), "=r"(r[2]), "=r"(r[3]) : "r"(a));
}

__device__ __forceinline__ void mma_bf16(float* c, const uint32_t* a,
                                         const uint32_t* b) {
    asm volatile(
        "mma.sync.aligned.m16n8k16.row.col.f32.bf16.bf16.f32 "
        "{%0,%1,%2,%3}, {%4,%5,%6,%7}, {%8,%9}, {%0,%1,%2,%3};"
        : "+f"(c[0]), "+f"(c[1]), "+f"(c[2]), "+f"(c[3])
        : "r"(a[0]), "r"(a[1]), "r"(a[2]), "r"(a[3]), "r"(b[0]), "r"(b[1]));
}

// Swizzled address for a 128-row x 64-byte tile packed 2-rows-per-128B line.
// a = (row/2)*128 + (row%2)*64 + cbyte;  XOR bits[4:6] with (row/2)%8.
// Conflict-free for 8-consecutive-row ldmatrix transactions at any 16B chunk.
__device__ __forceinline__ uint32_t swz(uint32_t row, uint32_t cbyte) {
    uint32_t a = ((row >> 1) << 7) + ((row & 1) << 6) + cbyte;
    return a ^ (((row >> 1) & 7) << 4);
}

// ---------------------------------------------------------------------------
// bf16x3-split tensor-core GEMM:  C[M,N] = alpha * A[M,K] @ Bt[N,K]^T (+ R)
// A row-major (M,K) hi/lo bf16; Bt row-major (N,K) hi/lo bf16.
// CTA tile 128x128, BK=32, 256 threads (8 warps, 4x2), warp tile 32x64.
// Unpadded XOR-swizzled 8KB tiles; stage = Ah|Al|Bh|Bl = 32KB.
// 3-stage cp.async ring, ONE __syncthreads per K-block, loads 2 stages
// ahead.  96KB smem -> 2 CTAs/SM;  __launch_bounds__(256,2) caps regs.
// ---------------------------------------------------------------------------
#define GEMM_DSMEM 98304

__global__ __launch_bounds__(256, 2) void gemm_mma_kernel(
    const __nv_bfloat16* __restrict__ Ah, const __nv_bfloat16* __restrict__ Al,
    const __nv_bfloat16* __restrict__ Bh, const __nv_bfloat16* __restrict__ Bl,
    const float* __restrict__ R, float* __restrict__ C,
    int Kdim, int Ndim, float alpha)
{
    extern __shared__ __nv_bfloat16 sm[];
    const int tid = threadIdx.x;
    const int lane = tid & 31;
    const int wid = tid >> 5;
    const int wm = wid & 3;        // 4 warp-rows (m)
    const int wn = wid >> 2;       // 2 warp-cols (n)
    const int bm = blockIdx.y * 128;
    const int bn = blockIdx.x * 128;
    const int nkb = Kdim >> 5;     // BK = 32

    const uint32_t smem_b = (uint32_t)__cvta_generic_to_shared(sm);

    float acc[2][8][4];
#pragma unroll
    for (int mt = 0; mt < 2; mt++)
#pragma unroll
        for (int nt = 0; nt < 8; nt++)
#pragma unroll
            for (int i = 0; i < 4; i++) acc[mt][nt][i] = 0.f;

    // cp.async stage load: 4 tiles x 128 rows x 4 16B-chunks = 2048 chunks,
    // 8 per thread.  tile order: 0=Ah 1=Al 2=Bh 3=Bl.  Always commits a
    // group (possibly empty past the end) so wait_group counts stay valid.
    auto load_stage = [&](int kb, int st) {
        if (kb < nkb) {
            const uint32_t base = smem_b + (uint32_t)st * 32768u;
#pragma unroll
            for (int i = 0; i < 8; i++) {
                const int t = i >> 1;                 // compile-time tile id
                int cc = tid + (i & 1) * 256;         // 0..511 within tile
                int row = cc >> 2, u = cc & 3;
                const __nv_bfloat16* p =
                    (t == 0 ? Ah : t == 1 ? Al : t == 2 ? Bh : Bl) +
                    (size_t)((t < 2 ? bm : bn) + row) * Kdim + kb * 32 + u * 8;
                cp16(base + (uint32_t)t * 8192u + swz((uint32_t)row,
                     (uint32_t)u * 16u), p);
            }
        }
        asm volatile("cp.async.commit_group;" ::: "memory");
    };

    // Precomputed per-lane swizzled fragment offsets (ks=0; ks=1 is ^32,
    // valid because base chunk offsets are in {0,16} and swizzle bits are
    // row-only).
    uint32_t aoff[2], boff[4];
#pragma unroll
    for (int mt = 0; mt < 2; mt++)
        aoff[mt] = swz((uint32_t)(wm * 32 + mt * 16 + (lane & 7) +
                                  8 * ((lane >> 3) & 1)),
                       (uint32_t)(16 * (lane >> 4)));
#pragma unroll
    for (int np = 0; np < 4; np++)
        boff[np] = swz((uint32_t)(wn * 64 + np * 16 + (lane & 7) +
                                  8 * (lane >> 4)),
                       (uint32_t)(16 * ((lane >> 3) & 1)));

    // Prologue: 2 stages in flight
    load_stage(0, 0);
    load_stage(1, 1);

    int st = 0;          // buffer for current kb
    int st2 = 2;         // buffer for kb+2
    for (int kb = 0; kb < nkb; kb++) {
        // stage kb landed once at most 1 newer group is still pending
        asm volatile("cp.async.wait_group 1;" ::: "memory");
        __syncthreads();   // all warps done reading buffer st2 (= kb-1's)
        load_stage(kb + 2, st2);

        const uint32_t sA  = smem_b + (uint32_t)st * 32768u;
        const uint32_t sAl = sA + 8192u;
        const uint32_t sBh = sA + 16384u;
        const uint32_t sBl = sA + 24576u;

#pragma unroll
        for (int ks = 0; ks < 2; ks++) {
            const uint32_t kx = (uint32_t)(ks * 32);

            uint32_t ah[2][4], al[2][4];
#pragma unroll
            for (int mt = 0; mt < 2; mt++) {
                uint32_t ad = aoff[mt] ^ kx;
                ldsm4(ah[mt], sA  + ad);
                ldsm4(al[mt], sAl + ad);
            }

            uint32_t bh[8][2], bl[8][2];
#pragma unroll
            for (int np = 0; np < 4; np++) {      // x4 covers two n8 tiles
                uint32_t bd = boff[np] ^ kx;
                uint32_t rh[4], rl[4];
                ldsm4(rh, sBh + bd);
                ldsm4(rl, sBl + bd);
                bh[2 * np][0] = rh[0]; bh[2 * np][1] = rh[1];
                bh[2 * np + 1][0] = rh[2]; bh[2 * np + 1][1] = rh[3];
                bl[2 * np][0] = rl[0]; bl[2 * np][1] = rl[1];
                bl[2 * np + 1][0] = rl[2]; bl[2 * np + 1][1] = rl[3];
            }

            // TERM-MAJOR: 16 independent MMAs between accumulator reuse.
#pragma unroll
            for (int mt = 0; mt < 2; mt++)
#pragma unroll
                for (int nt = 0; nt < 8; nt++)
                    mma_bf16(acc[mt][nt], ah[mt], bh[nt]);   // hi*hi
#pragma unroll
            for (int mt = 0; mt < 2; mt++)
#pragma unroll
                for (int nt = 0; nt < 8; nt++)
                    mma_bf16(acc[mt][nt], ah[mt], bl[nt]);   // hi*lo
#pragma unroll
            for (int mt = 0; mt < 2; mt++)
#pragma unroll
                for (int nt = 0; nt < 8; nt++)
                    mma_bf16(acc[mt][nt], al[mt], bh[nt]);   // lo*hi
        }

        // rotate ring indices (st -> next, st2 -> next)
        st  = (st  == 2) ? 0 : st + 1;
        st2 = (st2 == 2) ? 0 : st2 + 1;
    }

    // Epilogue: fragment layout -> float2 stores (+alpha, +residual)
#pragma unroll
    for (int mt = 0; mt < 2; mt++) {
        int row0 = bm + wm * 32 + mt * 16 + (lane >> 2);
#pragma unroll
        for (int nt = 0; nt < 8; nt++) {
            int col = bn + wn * 64 + nt * 8 + 2 * (lane & 3);
            size_t i0 = (size_t)row0 * Ndim + col;
            size_t i1 = i0 + (size_t)8 * Ndim;
            float2 v0, v1;
            v0.x = acc[mt][nt][0] * alpha;
            v0.y = acc[mt][nt][1] * alpha;
            v1.x = acc[mt][nt][2] * alpha;
            v1.y = acc[mt][nt][3] * alpha;
            if (R) {
                const float2 r0 = *(const float2*)(R + i0);
                const float2 r1 = *(const float2*)(R + i1);
                v0.x += r0.x; v0.y += r0.y;
                v1.x += r1.x; v1.y += r1.y;
            }
            *(float2*)(C + i0) = v0;
            *(float2*)(C + i1) = v1;
        }
    }
}

// ---------------------------------------------------------------------------
// fp32 -> bf16 hi/lo split (elementwise, float4)
// ---------------------------------------------------------------------------
__global__ __launch_bounds__(256) void split_kernel(
    const float* __restrict__ x,
    __nv_bfloat16* __restrict__ hi, __nv_bfloat16* __restrict__ lo, int n4)
{
    int i = blockIdx.x * 256 + threadIdx.x;
    if (i >= n4) return;
    float4 v = ((const float4*)x)[i];
    __nv_bfloat16 h0 = __float2bfloat16(v.x);
    __nv_bfloat16 h1 = __float2bfloat16(v.y);
    __nv_bfloat16 h2 = __float2bfloat16(v.z);
    __nv_bfloat16 h3 = __float2bfloat16(v.w);
    __nv_bfloat16 l0 = __float2bfloat16(v.x - __bfloat162float(h0));
    __nv_bfloat16 l1 = __float2bfloat16(v.y - __bfloat162float(h1));
    __nv_bfloat16 l2 = __float2bfloat16(v.z - __bfloat162float(h2));
    __nv_bfloat16 l3 = __float2bfloat16(v.w - __bfloat162float(h3));
    __nv_bfloat162 ph0; ph0.x = h0; ph0.y = h1;
    __nv_bfloat162 ph1; ph1.x = h2; ph1.y = h3;
    __nv_bfloat162 pl0; pl0.x = l0; pl0.y = l1;
    __nv_bfloat162 pl1; pl1.x = l2; pl1.y = l3;
    ((__nv_bfloat162*)hi)[2 * i]     = ph0;
    ((__nv_bfloat162*)hi)[2 * i + 1] = ph1;
    ((__nv_bfloat162*)lo)[2 * i]     = pl0;
    ((__nv_bfloat162*)lo)[2 * i + 1] = pl1;
}

// ---------------------------------------------------------------------------
// Transpose + split: W (K x N fp32) -> Wt hi/lo (N x K bf16)
// ---------------------------------------------------------------------------
__global__ __launch_bounds__(256) void tsplit_kernel(
    const float* __restrict__ W,
    __nv_bfloat16* __restrict__ hi, __nv_bfloat16* __restrict__ lo, int K, int N)
{
    __shared__ float t[32][33];
    const int tx = threadIdx.x, ty = threadIdx.y;  // 32 x 8
    const int bn = blockIdx.x * 32;
    const int bk = blockIdx.y * 32;
#pragma unroll
    for (int r = 0; r < 4; r++)
        t[ty + r * 8][tx] = W[(size_t)(bk + ty + r * 8) * N + bn + tx];
    __syncthreads();
#pragma unroll
    for (int r = 0; r < 4; r++) {
        int row = ty + r * 8;
        float v = t[tx][row];
        __nv_bfloat16 h = __float2bfloat16(v);
        __nv_bfloat16 l = __float2bfloat16(v - __bfloat162float(h));
        size_t idx = (size_t)(bn + row) * K + bk + tx;
        hi[idx] = h;
        lo[idx] = l;
    }
}

// ---------------------------------------------------------------------------
// Attention (unchanged; ~111us, DRAM-bound)
// ---------------------------------------------------------------------------
__global__ __launch_bounds__(128) void attn_kernel(
    const float* __restrict__ qb, const float* __restrict__ kb,
    const float* __restrict__ vb, float* __restrict__ ob)
{
    const int h = blockIdx.x;
    const int s = blockIdx.y;
    const int b = blockIdx.z;
    const int tid = threadIdx.x;
    const int lane = tid & 31;
    const int w = tid >> 5;

    __shared__ float sc[32];
    __shared__ float pr[32];

    const float* qv = qb + ((size_t)(b * S_ + s) * NH_ + h) * HD_;
    const float4 q4 = ((const float4*)qv)[lane];

    const int pprev = (s > 0) ? (s - 1) : 0;

#pragma unroll
    for (int j = 0; j < 8; j++) {
        int i = w * 8 + j;
        int p = (i < 16) ? pprev : s;
        int n = i & 15;
        const float* kr = kb + ((size_t)((b * S_ + p) * NN_ + h)) * (NH_ * HD_) + n * HD_;
        float4 k4 = ((const float4*)kr)[lane];
        float part = q4.x * k4.x + q4.y * k4.y + q4.z * k4.z + q4.w * k4.w;
#pragma unroll
        for (int off = 16; off; off >>= 1)
            part += __shfl_xor_sync(0xffffffffu, part, off);
        if (lane == 0) sc[i] = part;
    }
    __syncthreads();

    if (tid < 32) {
        float x = sc[tid];
        float m = x;
#pragma unroll
        for (int off = 16; off; off >>= 1)
            m = fmaxf(m, __shfl_xor_sync(0xffffffffu, m, off));
        float e = expf(x - m);
        float sum = e;
#pragma unroll
        for (int off = 16; off; off >>= 1)
            sum += __shfl_xor_sync(0xffffffffu, sum, off);
        pr[tid] = e / sum;
    }
    __syncthreads();

    float acc = 0.f;
    const int d = tid;
#pragma unroll 8
    for (int i = 0; i < 32; i++) {
        int p = (i < 16) ? pprev : s;
        int n = i & 15;
        acc += pr[i] * vb[((size_t)((b * S_ + p) * NN_ + h)) * (NH_ * HD_) + n * HD_ + d];
    }
    ob[((size_t)(b * S_ + s) * NH_ + h) * HD_ + d] = acc;
}

// ---------------------------------------------------------------------------
// Launch
// ---------------------------------------------------------------------------
extern "C" void kernel_launch(void* const* d_in, const int* in_sizes, int n_in,
                              void* d_out, int out_size)
{
    const float* hidden = (const float*)d_in[0];  // (B,S,HID)
    const float* ext    = (const float*)d_in[1];  // (B,S,NN,RHID)
    const float* Wq     = (const float*)d_in[2];  // (HID, 2048)
    const float* Wk     = (const float*)d_in[3];  // (RHID, 2048)
    const float* Wv     = (const float*)d_in[4];  // (RHID, 2048)
    const float* Wo     = (const float*)d_in[5];  // (2048, HID)
    float* out = (float*)d_out;

    float *q, *k, *v, *ao;
    cudaGetSymbolAddress((void**)&q,  g_q);
    cudaGetSymbolAddress((void**)&k,  g_k);
    cudaGetSymbolAddress((void**)&v,  g_v);
    cudaGetSymbolAddress((void**)&ao, g_ao);
    __nv_bfloat16 *exth, *extl, *hidh, *hidl, *aoh, *aol;
    __nv_bfloat16 *wqh, *wql, *wkh, *wkl, *wvh, *wvl, *woh, *wol;
    cudaGetSymbolAddress((void**)&exth, g_exth);
    cudaGetSymbolAddress((void**)&extl, g_extl);
    cudaGetSymbolAddress((void**)&hidh, g_hidh);
    cudaGetSymbolAddress((void**)&hidl, g_hidl);
    cudaGetSymbolAddress((void**)&aoh,  g_aoh);
    cudaGetSymbolAddress((void**)&aol,  g_aol);
    cudaGetSymbolAddress((void**)&wqh,  g_wqh);
    cudaGetSymbolAddress((void**)&wql,  g_wql);
    cudaGetSymbolAddress((void**)&wkh,  g_wkh);
    cudaGetSymbolAddress((void**)&wkl,  g_wkl);
    cudaGetSymbolAddress((void**)&wvh,  g_wvh);
    cudaGetSymbolAddress((void**)&wvl,  g_wvl);
    cudaGetSymbolAddress((void**)&woh,  g_woh);
    cudaGetSymbolAddress((void**)&wol,  g_wol);

    cudaFuncSetAttribute(gemm_mma_kernel,
                         cudaFuncAttributeMaxDynamicSharedMemorySize, GEMM_DSMEM);

    // Splits
    split_kernel<<<4096, 256>>>(hidden, hidh, hidl, 1048576);
    split_kernel<<<32768, 256>>>(ext, exth, extl, 8388608);
    // Weight transpose+split (W^T stored N x K)
    tsplit_kernel<<<dim3(64, 64), dim3(32, 8)>>>(Wq, wqh, wql, 2048, 2048);
    tsplit_kernel<<<dim3(64, 32), dim3(32, 8)>>>(Wk, wkh, wkl, 1024, 2048);
    tsplit_kernel<<<dim3(64, 32), dim3(32, 8)>>>(Wv, wvh, wvl, 1024, 2048);
    tsplit_kernel<<<dim3(64, 64), dim3(32, 8)>>>(Wo, woh, wol, 2048, 2048);

    // Q = hidden @ Wq * SCALE            (M=2048, N=2048, K=2048)
    gemm_mma_kernel<<<dim3(16, 16), 256, GEMM_DSMEM>>>(
        hidh, hidl, wqh, wql, nullptr, q, 2048, 2048, SCALE_);
    // K = ext @ Wk                       (M=32768, N=2048, K=1024)
    gemm_mma_kernel<<<dim3(16, 256), 256, GEMM_DSMEM>>>(
        exth, extl, wkh, wkl, nullptr, k, 1024, 2048, 1.0f);
    // V = ext @ Wv
    gemm_mma_kernel<<<dim3(16, 256), 256, GEMM_DSMEM>>>(
        exth, extl, wvh, wvl, nullptr, v, 1024, 2048, 1.0f);

    // Attention
    attn_kernel<<<dim3(NH_, S_, B_), dim3(128)>>>(q, k, v, ao);

    // out = ao @ Wo + hidden
    split_kernel<<<4096, 256>>>(ao, aoh, aol, 1048576);
    gemm_mma_kernel<<<dim3(16, 16), 256, GEMM_DSMEM>>>(
        aoh, aol, woh, wol, hidden, out, 2048, 2048, 1.0f);
}

// round 9
// speedup vs baseline: 3.2486x; 2.3087x over previous
#include <cuda_runtime.h>
#include <cuda_fp16.h>
#include <cstdint>
#include <cstddef>

// Problem constants
#define B_   2
#define S_   1024
#define HID_ 2048
#define NH_  16
#define HD_  128
#define NN_  16
#define RHID_ 1024
#define SCALE_ 0.08838834764831845f   // 128^-0.5

// ---------------------------------------------------------------------------
// Scratch (device globals: allocation-free per harness rules)
// ---------------------------------------------------------------------------
__device__ float g_q [4194304];     // (B*S, 2048) fp32
__device__ float g_k [67108864];    // (B*S*NN, 2048) fp32
__device__ float g_v [67108864];
__device__ float g_ao[4194304];

__device__ __half g_exth[33554432];   // ext fp16
__device__ __half g_hidh[4194304];    // hidden fp16
__device__ __half g_aoh [4194304];    // attn-out fp16
__device__ __half g_wqh [4194304];    // Wq^T fp16 (N x K)
__device__ __half g_wkh [2097152];    // Wk^T
__device__ __half g_wvh [2097152];    // Wv^T
__device__ __half g_woh [4194304];    // Wo^T

// ---------------------------------------------------------------------------
// PTX helpers (compute_103-safe: cp.async + ldmatrix + mma.sync only)
// ---------------------------------------------------------------------------
__device__ __forceinline__ void cp16(uint32_t dst, const void* src) {
    asm volatile("cp.async.cg.shared.global [%0], [%1], 16;"
                 :: "r"(dst), "l"(src) : "memory");
}

__device__ __forceinline__ void ldsm4(uint32_t* r, uint32_t a) {
    asm volatile("ldmatrix.sync.aligned.m8n8.x4.shared.b16 {%0,%1,%2,%3}, [%4];"
                 : "=r"(r[0]), "=r"(r[1]), "=r"(r[2]), "=r"(r[3]) : "r"(a));
}

__device__ __forceinline__ void mma_f16(float* c, const uint32_t* a,
                                        const uint32_t* b) {
    asm volatile(
        "mma.sync.aligned.m16n8k16.row.col.f32.f16.f16.f32 "
        "{%0,%1,%2,%3}, {%4,%5,%6,%7}, {%8,%9}, {%0,%1,%2,%3};"
        : "+f"(c[0]), "+f"(c[1]), "+f"(c[2]), "+f"(c[3])
        : "r"(a[0]), "r"(a[1]), "r"(a[2]), "r"(a[3]), "r"(b[0]), "r"(b[1]));
}

// Swizzled address for a 128-row x 64-byte tile packed 2-rows-per-128B line.
// a = (row/2)*128 + (row%2)*64 + cbyte;  XOR bits[4:6] with (row/2)%8.
// Conflict-free for 8-consecutive-row ldmatrix transactions at any 16B chunk.
__device__ __forceinline__ uint32_t swz(uint32_t row, uint32_t cbyte) {
    uint32_t a = ((row >> 1) << 7) + ((row & 1) << 6) + cbyte;
    return a ^ (((row >> 1) & 7) << 4);
}

// ---------------------------------------------------------------------------
// fp16 tensor-core GEMM:  C[M,N] = alpha * A[M,K] @ Bt[N,K]^T (+ R)
// A row-major (M,K) fp16; Bt row-major (N,K) fp16 (W transposed).
// CTA tile 128x128, BK=32, 256 threads (8 warps, 4x2), warp tile 32x64.
// Unpadded XOR-swizzled 8KB tiles; stage = A|B = 16KB.
// 3-stage cp.async ring, ONE __syncthreads per K-block, loads 2 ahead.
// ---------------------------------------------------------------------------
#define GEMM_DSMEM 49152

__global__ __launch_bounds__(256, 2) void gemm_mma_kernel(
    const __half* __restrict__ A, const __half* __restrict__ B,
    const float* __restrict__ R, float* __restrict__ C,
    int Kdim, int Ndim, float alpha)
{
    extern __shared__ __half sm[];
    const int tid = threadIdx.x;
    const int lane = tid & 31;
    const int wid = tid >> 5;
    const int wm = wid & 3;        // 4 warp-rows (m)
    const int wn = wid >> 2;       // 2 warp-cols (n)
    const int bm = blockIdx.y * 128;
    const int bn = blockIdx.x * 128;
    const int nkb = Kdim >> 5;     // BK = 32

    const uint32_t smem_b = (uint32_t)__cvta_generic_to_shared(sm);

    float acc[2][8][4];
#pragma unroll
    for (int mt = 0; mt < 2; mt++)
#pragma unroll
        for (int nt = 0; nt < 8; nt++)
#pragma unroll
            for (int i = 0; i < 4; i++) acc[mt][nt][i] = 0.f;

    // cp.async stage load: 2 tiles x 128 rows x 4 16B-chunks = 1024 chunks,
    // 4 per thread.  tile order: 0=A 1=B.
    auto load_stage = [&](int kb, int st) {
        if (kb < nkb) {
            const uint32_t base = smem_b + (uint32_t)st * 16384u;
#pragma unroll
            for (int i = 0; i < 4; i++) {
                const int t = i >> 1;                 // compile-time tile id
                int cc = tid + (i & 1) * 256;         // 0..511 within tile
                int row = cc >> 2, u = cc & 3;
                const __half* p = (t == 0 ? A : B) +
                    (size_t)((t == 0 ? bm : bn) + row) * Kdim + kb * 32 + u * 8;
                cp16(base + (uint32_t)t * 8192u + swz((uint32_t)row,
                     (uint32_t)u * 16u), p);
            }
        }
        asm volatile("cp.async.commit_group;" ::: "memory");
    };

    // Precomputed per-lane swizzled fragment offsets (ks=0; ks=1 is ^32,
    // valid because base chunk offsets are in {0,16} and swizzle bits are
    // row-only).
    uint32_t aoff[2], boff[4];
#pragma unroll
    for (int mt = 0; mt < 2; mt++)
        aoff[mt] = swz((uint32_t)(wm * 32 + mt * 16 + (lane & 7) +
                                  8 * ((lane >> 3) & 1)),
                       (uint32_t)(16 * (lane >> 4)));
#pragma unroll
    for (int np = 0; np < 4; np++)
        boff[np] = swz((uint32_t)(wn * 64 + np * 16 + (lane & 7) +
                                  8 * (lane >> 4)),
                       (uint32_t)(16 * ((lane >> 3) & 1)));

    // Prologue: 2 stages in flight
    load_stage(0, 0);
    load_stage(1, 1);

    int st = 0;          // buffer for current kb
    int st2 = 2;         // buffer for kb+2
    for (int kb = 0; kb < nkb; kb++) {
        // stage kb landed once at most 1 newer group is still pending
        asm volatile("cp.async.wait_group 1;" ::: "memory");
        __syncthreads();   // all warps done reading buffer st2 (= kb-1's)
        load_stage(kb + 2, st2);

        const uint32_t sA = smem_b + (uint32_t)st * 16384u;
        const uint32_t sB = sA + 8192u;

#pragma unroll
        for (int ks = 0; ks < 2; ks++) {
            const uint32_t kx = (uint32_t)(ks * 32);

            uint32_t ah[2][4];
#pragma unroll
            for (int mt = 0; mt < 2; mt++)
                ldsm4(ah[mt], sA + (aoff[mt] ^ kx));

            uint32_t bh[8][2];
#pragma unroll
            for (int np = 0; np < 4; np++) {      // x4 covers two n8 tiles
                uint32_t rh[4];
                ldsm4(rh, sB + (boff[np] ^ kx));
                bh[2 * np][0] = rh[0]; bh[2 * np][1] = rh[1];
                bh[2 * np + 1][0] = rh[2]; bh[2 * np + 1][1] = rh[3];
            }

#pragma unroll
            for (int mt = 0; mt < 2; mt++)
#pragma unroll
                for (int nt = 0; nt < 8; nt++)
                    mma_f16(acc[mt][nt], ah[mt], bh[nt]);
        }

        // rotate ring indices
        st  = (st  == 2) ? 0 : st + 1;
        st2 = (st2 == 2) ? 0 : st2 + 1;
    }

    // Epilogue: fragment layout -> float2 stores (+alpha, +residual)
#pragma unroll
    for (int mt = 0; mt < 2; mt++) {
        int row0 = bm + wm * 32 + mt * 16 + (lane >> 2);
#pragma unroll
        for (int nt = 0; nt < 8; nt++) {
            int col = bn + wn * 64 + nt * 8 + 2 * (lane & 3);
            size_t i0 = (size_t)row0 * Ndim + col;
            size_t i1 = i0 + (size_t)8 * Ndim;
            float2 v0, v1;
            v0.x = acc[mt][nt][0] * alpha;
            v0.y = acc[mt][nt][1] * alpha;
            v1.x = acc[mt][nt][2] * alpha;
            v1.y = acc[mt][nt][3] * alpha;
            if (R) {
                const float2 r0 = *(const float2*)(R + i0);
                const float2 r1 = *(const float2*)(R + i1);
                v0.x += r0.x; v0.y += r0.y;
                v1.x += r1.x; v1.y += r1.y;
            }
            *(float2*)(C + i0) = v0;
            *(float2*)(C + i1) = v1;
        }
    }
}

// ---------------------------------------------------------------------------
// fp32 -> fp16 convert (elementwise, float4)
// ---------------------------------------------------------------------------
__global__ __launch_bounds__(256) void cvt_kernel(
    const float* __restrict__ x, __half* __restrict__ h, int n4)
{
    int i = blockIdx.x * 256 + threadIdx.x;
    if (i >= n4) return;
    float4 v = ((const float4*)x)[i];
    __half2 p0 = __floats2half2_rn(v.x, v.y);
    __half2 p1 = __floats2half2_rn(v.z, v.w);
    ((__half2*)h)[2 * i]     = p0;
    ((__half2*)h)[2 * i + 1] = p1;
}

// ---------------------------------------------------------------------------
// Transpose + convert: W (K x N fp32) -> Wt (N x K fp16)
// ---------------------------------------------------------------------------
__global__ __launch_bounds__(256) void tcvt_kernel(
    const float* __restrict__ W, __half* __restrict__ h, int K, int N)
{
    __shared__ float t[32][33];
    const int tx = threadIdx.x, ty = threadIdx.y;  // 32 x 8
    const int bn = blockIdx.x * 32;
    const int bk = blockIdx.y * 32;
#pragma unroll
    for (int r = 0; r < 4; r++)
        t[ty + r * 8][tx] = W[(size_t)(bk + ty + r * 8) * N + bn + tx];
    __syncthreads();
#pragma unroll
    for (int r = 0; r < 4; r++) {
        int row = ty + r * 8;
        h[(size_t)(bn + row) * K + bk + tx] = __float2half_rn(t[tx][row]);
    }
}

// ---------------------------------------------------------------------------
// Attention (unchanged; DRAM-bound, ~111us)
// ---------------------------------------------------------------------------
__global__ __launch_bounds__(128) void attn_kernel(
    const float* __restrict__ qb, const float* __restrict__ kb,
    const float* __restrict__ vb, float* __restrict__ ob)
{
    const int h = blockIdx.x;
    const int s = blockIdx.y;
    const int b = blockIdx.z;
    const int tid = threadIdx.x;
    const int lane = tid & 31;
    const int w = tid >> 5;

    __shared__ float sc[32];
    __shared__ float pr[32];

    const float* qv = qb + ((size_t)(b * S_ + s) * NH_ + h) * HD_;
    const float4 q4 = ((const float4*)qv)[lane];

    const int pprev = (s > 0) ? (s - 1) : 0;

#pragma unroll
    for (int j = 0; j < 8; j++) {
        int i = w * 8 + j;
        int p = (i < 16) ? pprev : s;
        int n = i & 15;
        const float* kr = kb + ((size_t)((b * S_ + p) * NN_ + h)) * (NH_ * HD_) + n * HD_;
        float4 k4 = ((const float4*)kr)[lane];
        float part = q4.x * k4.x + q4.y * k4.y + q4.z * k4.z + q4.w * k4.w;
#pragma unroll
        for (int off = 16; off; off >>= 1)
            part += __shfl_xor_sync(0xffffffffu, part, off);
        if (lane == 0) sc[i] = part;
    }
    __syncthreads();

    if (tid < 32) {
        float x = sc[tid];
        float m = x;
#pragma unroll
        for (int off = 16; off; off >>= 1)
            m = fmaxf(m, __shfl_xor_sync(0xffffffffu, m, off));
        float e = expf(x - m);
        float sum = e;
#pragma unroll
        for (int off = 16; off; off >>= 1)
            sum += __shfl_xor_sync(0xffffffffu, sum, off);
        pr[tid] = e / sum;
    }
    __syncthreads();

    float acc = 0.f;
    const int d = tid;
#pragma unroll 8
    for (int i = 0; i < 32; i++) {
        int p = (i < 16) ? pprev : s;
        int n = i & 15;
        acc += pr[i] * vb[((size_t)((b * S_ + p) * NN_ + h)) * (NH_ * HD_) + n * HD_ + d];
    }
    ob[((size_t)(b * S_ + s) * NH_ + h) * HD_ + d] = acc;
}

// ---------------------------------------------------------------------------
// Launch — ordered so launch #6 (ncu -s 5 -c 1 capture) is the big K-GEMM.
// ---------------------------------------------------------------------------
extern "C" void kernel_launch(void* const* d_in, const int* in_sizes, int n_in,
                              void* d_out, int out_size)
{
    const float* hidden = (const float*)d_in[0];  // (B,S,HID)
    const float* ext    = (const float*)d_in[1];  // (B,S,NN,RHID)
    const float* Wq     = (const float*)d_in[2];  // (HID, 2048)
    const float* Wk     = (const float*)d_in[3];  // (RHID, 2048)
    const float* Wv     = (const float*)d_in[4];  // (RHID, 2048)
    const float* Wo     = (const float*)d_in[5];  // (2048, HID)
    float* out = (float*)d_out;

    float *q, *k, *v, *ao;
    cudaGetSymbolAddress((void**)&q,  g_q);
    cudaGetSymbolAddress((void**)&k,  g_k);
    cudaGetSymbolAddress((void**)&v,  g_v);
    cudaGetSymbolAddress((void**)&ao, g_ao);
    __half *exth, *hidh, *aoh, *wqh, *wkh, *wvh, *woh;
    cudaGetSymbolAddress((void**)&exth, g_exth);
    cudaGetSymbolAddress((void**)&hidh, g_hidh);
    cudaGetSymbolAddress((void**)&aoh,  g_aoh);
    cudaGetSymbolAddress((void**)&wqh,  g_wqh);
    cudaGetSymbolAddress((void**)&wkh,  g_wkh);
    cudaGetSymbolAddress((void**)&wvh,  g_wvh);
    cudaGetSymbolAddress((void**)&woh,  g_woh);

    cudaFuncSetAttribute(gemm_mma_kernel,
                         cudaFuncAttributeMaxDynamicSharedMemorySize, GEMM_DSMEM);

    // 1-5: converts feeding the K GEMM (so launch #6 is gemm K for ncu)
    cvt_kernel<<<4096, 256>>>(hidden, hidh, 1048576);                 // 1
    cvt_kernel<<<32768, 256>>>(ext, exth, 8388608);                   // 2
    tcvt_kernel<<<dim3(64, 64), dim3(32, 8)>>>(Wq, wqh, 2048, 2048);  // 3
    tcvt_kernel<<<dim3(64, 32), dim3(32, 8)>>>(Wk, wkh, 1024, 2048);  // 4
    tcvt_kernel<<<dim3(64, 32), dim3(32, 8)>>>(Wv, wvh, 1024, 2048);  // 5

    // 6: K = ext @ Wk   (M=32768, N=2048, K=1024)  <- ncu capture target
    gemm_mma_kernel<<<dim3(16, 256), 256, GEMM_DSMEM>>>(
        exth, wkh, nullptr, k, 1024, 2048, 1.0f);
    // 7: V = ext @ Wv
    gemm_mma_kernel<<<dim3(16, 256), 256, GEMM_DSMEM>>>(
        exth, wvh, nullptr, v, 1024, 2048, 1.0f);
    // 8: Q = hidden @ Wq * SCALE   (M=2048, N=2048, K=2048)
    gemm_mma_kernel<<<dim3(16, 16), 256, GEMM_DSMEM>>>(
        hidh, wqh, nullptr, q, 2048, 2048, SCALE_);

    // 9: Wo transpose+convert
    tcvt_kernel<<<dim3(64, 64), dim3(32, 8)>>>(Wo, woh, 2048, 2048);

    // 10: attention
    attn_kernel<<<dim3(NH_, S_, B_), dim3(128)>>>(q, k, v, ao);

    // 11-12: out = ao @ Wo + hidden
    cvt_kernel<<<4096, 256>>>(ao, aoh, 1048576);
    gemm_mma_kernel<<<dim3(16, 16), 256, GEMM_DSMEM>>>(
        aoh, woh, hidden, out, 2048, 2048, 1.0f);
}

// round 10
// speedup vs baseline: 3.2855x; 1.0113x over previous
#include <cuda_runtime.h>
#include <cuda_fp16.h>
#include <cstdint>
#include <cstddef>

// Problem constants
#define B_   2
#define S_   1024
#define HID_ 2048
#define NH_  16
#define HD_  128
#define NN_  16
#define RHID_ 1024
#define SCALE_ 0.08838834764831845f   // 128^-0.5

// ---------------------------------------------------------------------------
// Scratch (device globals: allocation-free per harness rules)
// ---------------------------------------------------------------------------
__device__ __half g_qh [4194304];     // (B*S, 2048) fp16
__device__ __half g_kh [67108864];    // (B*S*NN, 2048) fp16
__device__ __half g_vh [67108864];
__device__ __half g_aoh[4194304];     // attention output fp16

__device__ __half g_exth[33554432];   // ext fp16
__device__ __half g_hidh[4194304];    // hidden fp16
__device__ __half g_wqh [4194304];    // Wq^T fp16 (N x K)
__device__ __half g_wkh [2097152];    // Wk^T
__device__ __half g_wvh [2097152];    // Wv^T
__device__ __half g_woh [4194304];    // Wo^T

// ---------------------------------------------------------------------------
// PTX helpers (compute_103-safe: cp.async + ldmatrix + mma.sync only)
// ---------------------------------------------------------------------------
__device__ __forceinline__ void cp16(uint32_t dst, const void* src) {
    asm volatile("cp.async.cg.shared.global [%0], [%1], 16;"
                 :: "r"(dst), "l"(src) : "memory");
}

__device__ __forceinline__ void ldsm4(uint32_t* r, uint32_t a) {
    asm volatile("ldmatrix.sync.aligned.m8n8.x4.shared.b16 {%0,%1,%2,%3}, [%4];"
                 : "=r"(r[0]), "=r"(r[1]), "=r"(r[2]), "=r"(r[3]) : "r"(a));
}

__device__ __forceinline__ void mma_f16(float* c, const uint32_t* a,
                                        const uint32_t* b) {
    asm volatile(
        "mma.sync.aligned.m16n8k16.row.col.f32.f16.f16.f32 "
        "{%0,%1,%2,%3}, {%4,%5,%6,%7}, {%8,%9}, {%0,%1,%2,%3};"
        : "+f"(c[0]), "+f"(c[1]), "+f"(c[2]), "+f"(c[3])
        : "r"(a[0]), "r"(a[1]), "r"(a[2]), "r"(a[3]), "r"(b[0]), "r"(b[1]));
}

// Swizzled address for a 128-row x 64-byte tile packed 2-rows-per-128B line.
__device__ __forceinline__ uint32_t swz(uint32_t row, uint32_t cbyte) {
    uint32_t a = ((row >> 1) << 7) + ((row & 1) << 6) + cbyte;
    return a ^ (((row >> 1) & 7) << 4);
}

// ---------------------------------------------------------------------------
// fp16 tensor-core GEMM:  C[M,N] = alpha * A[M,K] @ Bt[N,K]^T (+ R)
// HALF_OUT=true: C is fp16, no residual.  false: C fp32 (+ optional R).
// CTA tile 128x128, BK=32, 256 threads (8 warps, 4x2), warp tile 32x64.
// 3-stage cp.async ring, one __syncthreads per K-block.
// ---------------------------------------------------------------------------
#define GEMM_DSMEM 49152

template <bool HALF_OUT>
__global__ __launch_bounds__(256, 2) void gemm_mma_kernel(
    const __half* __restrict__ A, const __half* __restrict__ B,
    const float* __restrict__ R, void* __restrict__ Cv,
    int Kdim, int Ndim, float alpha)
{
    extern __shared__ __half sm[];
    const int tid = threadIdx.x;
    const int lane = tid & 31;
    const int wid = tid >> 5;
    const int wm = wid & 3;        // 4 warp-rows (m)
    const int wn = wid >> 2;       // 2 warp-cols (n)
    const int bm = blockIdx.y * 128;
    const int bn = blockIdx.x * 128;
    const int nkb = Kdim >> 5;     // BK = 32

    const uint32_t smem_b = (uint32_t)__cvta_generic_to_shared(sm);

    float acc[2][8][4];
#pragma unroll
    for (int mt = 0; mt < 2; mt++)
#pragma unroll
        for (int nt = 0; nt < 8; nt++)
#pragma unroll
            for (int i = 0; i < 4; i++) acc[mt][nt][i] = 0.f;

    auto load_stage = [&](int kb, int st) {
        if (kb < nkb) {
            const uint32_t base = smem_b + (uint32_t)st * 16384u;
#pragma unroll
            for (int i = 0; i < 4; i++) {
                const int t = i >> 1;                 // 0=A 1=B
                int cc = tid + (i & 1) * 256;         // 0..511 within tile
                int row = cc >> 2, u = cc & 3;
                const __half* p = (t == 0 ? A : B) +
                    (size_t)((t == 0 ? bm : bn) + row) * Kdim + kb * 32 + u * 8;
                cp16(base + (uint32_t)t * 8192u + swz((uint32_t)row,
                     (uint32_t)u * 16u), p);
            }
        }
        asm volatile("cp.async.commit_group;" ::: "memory");
    };

    uint32_t aoff[2], boff[4];
#pragma unroll
    for (int mt = 0; mt < 2; mt++)
        aoff[mt] = swz((uint32_t)(wm * 32 + mt * 16 + (lane & 7) +
                                  8 * ((lane >> 3) & 1)),
                       (uint32_t)(16 * (lane >> 4)));
#pragma unroll
    for (int np = 0; np < 4; np++)
        boff[np] = swz((uint32_t)(wn * 64 + np * 16 + (lane & 7) +
                                  8 * (lane >> 4)),
                       (uint32_t)(16 * ((lane >> 3) & 1)));

    load_stage(0, 0);
    load_stage(1, 1);

    int st = 0, st2 = 2;
    for (int kb = 0; kb < nkb; kb++) {
        asm volatile("cp.async.wait_group 1;" ::: "memory");
        __syncthreads();
        load_stage(kb + 2, st2);

        const uint32_t sA = smem_b + (uint32_t)st * 16384u;
        const uint32_t sB = sA + 8192u;

#pragma unroll
        for (int ks = 0; ks < 2; ks++) {
            const uint32_t kx = (uint32_t)(ks * 32);

            uint32_t ah[2][4];
#pragma unroll
            for (int mt = 0; mt < 2; mt++)
                ldsm4(ah[mt], sA + (aoff[mt] ^ kx));

            uint32_t bh[8][2];
#pragma unroll
            for (int np = 0; np < 4; np++) {
                uint32_t rh[4];
                ldsm4(rh, sB + (boff[np] ^ kx));
                bh[2 * np][0] = rh[0]; bh[2 * np][1] = rh[1];
                bh[2 * np + 1][0] = rh[2]; bh[2 * np + 1][1] = rh[3];
            }

#pragma unroll
            for (int mt = 0; mt < 2; mt++)
#pragma unroll
                for (int nt = 0; nt < 8; nt++)
                    mma_f16(acc[mt][nt], ah[mt], bh[nt]);
        }

        st  = (st  == 2) ? 0 : st + 1;
        st2 = (st2 == 2) ? 0 : st2 + 1;
    }

    // Epilogue
#pragma unroll
    for (int mt = 0; mt < 2; mt++) {
        int row0 = bm + wm * 32 + mt * 16 + (lane >> 2);
#pragma unroll
        for (int nt = 0; nt < 8; nt++) {
            int col = bn + wn * 64 + nt * 8 + 2 * (lane & 3);
            size_t i0 = (size_t)row0 * Ndim + col;
            size_t i1 = i0 + (size_t)8 * Ndim;
            if (HALF_OUT) {
                __half* C = (__half*)Cv;
                __half2 h0 = __floats2half2_rn(acc[mt][nt][0] * alpha,
                                               acc[mt][nt][1] * alpha);
                __half2 h1 = __floats2half2_rn(acc[mt][nt][2] * alpha,
                                               acc[mt][nt][3] * alpha);
                *(__half2*)(C + i0) = h0;
                *(__half2*)(C + i1) = h1;
            } else {
                float* C = (float*)Cv;
                float2 v0, v1;
                v0.x = acc[mt][nt][0] * alpha;
                v0.y = acc[mt][nt][1] * alpha;
                v1.x = acc[mt][nt][2] * alpha;
                v1.y = acc[mt][nt][3] * alpha;
                if (R) {
                    const float2 r0 = *(const float2*)(R + i0);
                    const float2 r1 = *(const float2*)(R + i1);
                    v0.x += r0.x; v0.y += r0.y;
                    v1.x += r1.x; v1.y += r1.y;
                }
                *(float2*)(C + i0) = v0;
                *(float2*)(C + i1) = v1;
            }
        }
    }
}

// ---------------------------------------------------------------------------
// fp32 -> fp16 convert (elementwise, float4)
// ---------------------------------------------------------------------------
__global__ __launch_bounds__(256) void cvt_kernel(
    const float* __restrict__ x, __half* __restrict__ h, int n4)
{
    int i = blockIdx.x * 256 + threadIdx.x;
    if (i >= n4) return;
    float4 v = ((const float4*)x)[i];
    ((__half2*)h)[2 * i]     = __floats2half2_rn(v.x, v.y);
    ((__half2*)h)[2 * i + 1] = __floats2half2_rn(v.z, v.w);
}

// ---------------------------------------------------------------------------
// Transpose + convert: W (K x N fp32) -> Wt (N x K fp16)
// ---------------------------------------------------------------------------
__global__ __launch_bounds__(256) void tcvt_kernel(
    const float* __restrict__ W, __half* __restrict__ h, int K, int N)
{
    __shared__ float t[32][33];
    const int tx = threadIdx.x, ty = threadIdx.y;  // 32 x 8
    const int bn = blockIdx.x * 32;
    const int bk = blockIdx.y * 32;
#pragma unroll
    for (int r = 0; r < 4; r++)
        t[ty + r * 8][tx] = W[(size_t)(bk + ty + r * 8) * N + bn + tx];
    __syncthreads();
#pragma unroll
    for (int r = 0; r < 4; r++) {
        int row = ty + r * 8;
        h[(size_t)(bn + row) * K + bk + tx] = __float2half_rn(t[tx][row]);
    }
}

// ---------------------------------------------------------------------------
// Attention — fp16 Q/K/V in, fp16 out.  Per (b,s,h) block of 128 threads.
// ---------------------------------------------------------------------------
__global__ __launch_bounds__(128) void attn_kernel(
    const __half* __restrict__ qb, const __half* __restrict__ kb,
    const __half* __restrict__ vb, __half* __restrict__ ob)
{
    const int h = blockIdx.x;
    const int s = blockIdx.y;
    const int b = blockIdx.z;
    const int tid = threadIdx.x;
    const int lane = tid & 31;
    const int w = tid >> 5;

    __shared__ float sc[32];
    __shared__ float pr[32];

    // lane covers dims 4*lane .. 4*lane+3 (8B = float2 of 4 halves)
    const __half* qv = qb + ((size_t)(b * S_ + s) * NH_ + h) * HD_;
    float2 qraw = ((const float2*)qv)[lane];
    __half2 q01 = *(__half2*)&qraw.x;
    __half2 q23 = *(__half2*)&qraw.y;
    float2 qf0 = __half22float2(q01);
    float2 qf1 = __half22float2(q23);

    const int pprev = (s > 0) ? (s - 1) : 0;

#pragma unroll
    for (int j = 0; j < 8; j++) {
        int i = w * 8 + j;
        int p = (i < 16) ? pprev : s;
        int n = i & 15;
        const __half* kr = kb + ((size_t)((b * S_ + p) * NN_ + h)) * (NH_ * HD_) + n * HD_;
        float2 kraw = ((const float2*)kr)[lane];
        __half2 k01 = *(__half2*)&kraw.x;
        __half2 k23 = *(__half2*)&kraw.y;
        float2 kf0 = __half22float2(k01);
        float2 kf1 = __half22float2(k23);
        float part = qf0.x * kf0.x + qf0.y * kf0.y + qf1.x * kf1.x + qf1.y * kf1.y;
#pragma unroll
        for (int off = 16; off; off >>= 1)
            part += __shfl_xor_sync(0xffffffffu, part, off);
        if (lane == 0) sc[i] = part;
    }
    __syncthreads();

    if (tid < 32) {
        float x = sc[tid];
        float m = x;
#pragma unroll
        for (int off = 16; off; off >>= 1)
            m = fmaxf(m, __shfl_xor_sync(0xffffffffu, m, off));
        float e = expf(x - m);
        float sum = e;
#pragma unroll
        for (int off = 16; off; off >>= 1)
            sum += __shfl_xor_sync(0xffffffffu, sum, off);
        pr[tid] = e / sum;
    }
    __syncthreads();

    float acc = 0.f;
    const int d = tid;
#pragma unroll 8
    for (int i = 0; i < 32; i++) {
        int p = (i < 16) ? pprev : s;
        int n = i & 15;
        acc += pr[i] * __half2float(
            vb[((size_t)((b * S_ + p) * NN_ + h)) * (NH_ * HD_) + n * HD_ + d]);
    }
    ob[((size_t)(b * S_ + s) * NH_ + h) * HD_ + d] = __float2half_rn(acc);
}

// ---------------------------------------------------------------------------
// Launch — ordered so launch #6 (ncu -s 5 -c 1 capture) is the big K-GEMM.
// ---------------------------------------------------------------------------
extern "C" void kernel_launch(void* const* d_in, const int* in_sizes, int n_in,
                              void* d_out, int out_size)
{
    const float* hidden = (const float*)d_in[0];  // (B,S,HID)
    const float* ext    = (const float*)d_in[1];  // (B,S,NN,RHID)
    const float* Wq     = (const float*)d_in[2];  // (HID, 2048)
    const float* Wk     = (const float*)d_in[3];  // (RHID, 2048)
    const float* Wv     = (const float*)d_in[4];  // (RHID, 2048)
    const float* Wo     = (const float*)d_in[5];  // (2048, HID)
    float* out = (float*)d_out;

    __half *qh, *kh, *vh, *aoh, *exth, *hidh, *wqh, *wkh, *wvh, *woh;
    cudaGetSymbolAddress((void**)&qh,   g_qh);
    cudaGetSymbolAddress((void**)&kh,   g_kh);
    cudaGetSymbolAddress((void**)&vh,   g_vh);
    cudaGetSymbolAddress((void**)&aoh,  g_aoh);
    cudaGetSymbolAddress((void**)&exth, g_exth);
    cudaGetSymbolAddress((void**)&hidh, g_hidh);
    cudaGetSymbolAddress((void**)&wqh,  g_wqh);
    cudaGetSymbolAddress((void**)&wkh,  g_wkh);
    cudaGetSymbolAddress((void**)&wvh,  g_wvh);
    cudaGetSymbolAddress((void**)&woh,  g_woh);

    cudaFuncSetAttribute(gemm_mma_kernel<true>,
                         cudaFuncAttributeMaxDynamicSharedMemorySize, GEMM_DSMEM);
    cudaFuncSetAttribute(gemm_mma_kernel<false>,
                         cudaFuncAttributeMaxDynamicSharedMemorySize, GEMM_DSMEM);

    // 1-5: converts feeding the K GEMM (launch #6 = gemm K for ncu)
    cvt_kernel<<<4096, 256>>>(hidden, hidh, 1048576);                 // 1
    cvt_kernel<<<32768, 256>>>(ext, exth, 8388608);                   // 2
    tcvt_kernel<<<dim3(64, 64), dim3(32, 8)>>>(Wq, wqh, 2048, 2048);  // 3
    tcvt_kernel<<<dim3(64, 32), dim3(32, 8)>>>(Wk, wkh, 1024, 2048);  // 4
    tcvt_kernel<<<dim3(64, 32), dim3(32, 8)>>>(Wv, wvh, 1024, 2048);  // 5

    // 6: K = ext @ Wk  (fp16 out)   <- ncu capture target
    gemm_mma_kernel<true><<<dim3(16, 256), 256, GEMM_DSMEM>>>(
        exth, wkh, nullptr, kh, 1024, 2048, 1.0f);
    // 7: V = ext @ Wv  (fp16 out)
    gemm_mma_kernel<true><<<dim3(16, 256), 256, GEMM_DSMEM>>>(
        exth, wvh, nullptr, vh, 1024, 2048, 1.0f);
    // 8: Q = hidden @ Wq * SCALE  (fp16 out)
    gemm_mma_kernel<true><<<dim3(16, 16), 256, GEMM_DSMEM>>>(
        hidh, wqh, nullptr, qh, 2048, 2048, SCALE_);

    // 9: Wo transpose+convert
    tcvt_kernel<<<dim3(64, 64), dim3(32, 8)>>>(Wo, woh, 2048, 2048);

    // 10: attention (fp16 in/out)
    attn_kernel<<<dim3(NH_, S_, B_), dim3(128)>>>(qh, kh, vh, aoh);

    // 11: out = ao @ Wo + hidden  (fp32 out + residual)
    gemm_mma_kernel<false><<<dim3(16, 16), 256, GEMM_DSMEM>>>(
        aoh, woh, hidden, out, 2048, 2048, 1.0f);
}